// round 1
// baseline (speedup 1.0000x reference)
#include <cuda_runtime.h>

// Problem constants
#define B_   2
#define S_   2048
#define E_   1024
#define H_   16
#define D_   64
#define HD_  1024
#define N_   4096            // B*S
#define SCALE_ 0.125f        // 1/sqrt(64)
#define NEG_  -1e9f

// ---------------- scratch (device globals; no allocations allowed) -------
__device__ float g_q[(size_t)B_ * H_ * S_ * D_];    // [bh][s][d]
__device__ float g_k[(size_t)B_ * H_ * S_ * D_];
__device__ float g_v[(size_t)B_ * H_ * S_ * D_];
__device__ float g_ctx[(size_t)N_ * HD_];           // [b*S+s][h*D+d]
__device__ int   g_mask_mode;                       // 0=u8, 1=i32, 2=f32

// ---------------- mask dtype detector ------------------------------------
__global__ void detect_mask_kernel(const unsigned int* __restrict__ m) {
    unsigned int v = m[threadIdx.x];          // first 1024 bytes / 256 words
    int isf = (v == 0x3F800000u);
    int big = (v > 1u);
    isf = __syncthreads_or(isf);
    big = __syncthreads_or(big);
    if (threadIdx.x == 0) g_mask_mode = isf ? 2 : (big ? 0 : 1);
}

// ---------------- GEMM: out = A[4096,1024] @ W[1024,1024] + bias ---------
// sel: 0/1/2 -> store to g_q/g_k/g_v in [B,H,S,D] layout; 3 -> A=g_ctx, flat store to outp
__global__ void __launch_bounds__(256) gemm_kernel(
    const float* __restrict__ Ain, const float* __restrict__ W,
    const float* __restrict__ bias, float* __restrict__ outp, int sel) {

    __shared__ float Ast[16 * 64];   // [kk][r]  (A tile transposed)
    __shared__ float Bs [16 * 64];   // [kk][col]

    const float* A = (sel == 3) ? g_ctx : Ain;
    float* dst = (sel == 0) ? g_q : (sel == 1) ? g_k : (sel == 2) ? g_v : outp;

    const int tid = threadIdx.x;
    const int tx = tid & 15, ty = tid >> 4;
    const int n0 = blockIdx.y * 64, c0 = blockIdx.x * 64;

    const int rA = tid >> 2, kqA = (tid & 3) << 2;   // A loader: row, k-quad
    const int kkB = tid >> 4, jB = (tid & 15) << 2;  // B loader

    float acc[4][4] = {};

    for (int k0 = 0; k0 < E_; k0 += 16) {
        float4 a = *(const float4*)(A + (size_t)(n0 + rA) * E_ + k0 + kqA);
        Ast[(kqA + 0) * 64 + rA] = a.x;
        Ast[(kqA + 1) * 64 + rA] = a.y;
        Ast[(kqA + 2) * 64 + rA] = a.z;
        Ast[(kqA + 3) * 64 + rA] = a.w;
        *(float4*)(Bs + kkB * 64 + jB) =
            *(const float4*)(W + (size_t)(k0 + kkB) * HD_ + c0 + jB);
        __syncthreads();

#pragma unroll
        for (int kk = 0; kk < 16; kk++) {
            float4 a4 = *(const float4*)(Ast + kk * 64 + ty * 4);
            float4 b4 = *(const float4*)(Bs  + kk * 64 + tx * 4);
            float av[4] = {a4.x, a4.y, a4.z, a4.w};
            float bv[4] = {b4.x, b4.y, b4.z, b4.w};
#pragma unroll
            for (int ir = 0; ir < 4; ir++)
#pragma unroll
                for (int jc = 0; jc < 4; jc++)
                    acc[ir][jc] = fmaf(av[ir], bv[jc], acc[ir][jc]);
        }
        __syncthreads();
    }

    float4 bb = *(const float4*)(bias + c0 + tx * 4);
    float bv2[4] = {bb.x, bb.y, bb.z, bb.w};

#pragma unroll
    for (int ir = 0; ir < 4; ir++) {
        int row = n0 + ty * 4 + ir;
        float4 o = make_float4(acc[ir][0] + bv2[0], acc[ir][1] + bv2[1],
                               acc[ir][2] + bv2[2], acc[ir][3] + bv2[3]);
        if (sel < 3) {
            int bI = row >> 11, sI = row & (S_ - 1);
            int col = c0 + tx * 4;
            int hI = col >> 6, dI = col & 63;
            *(float4*)(dst + (((size_t)bI * H_ + hI) * S_ + sI) * D_ + dI) = o;
        } else {
            *(float4*)(dst + (size_t)row * E_ + c0 + tx * 4) = o;
        }
    }
}

// ---------------- attention: scores->softmax->prob + context -------------
// grid: (S/64, B*H). Pass 1 writes masked scaled scores into the prob output
// region (scratch) and tracks online (m,l). Pass 2 re-reads the same elements
// (same thread wrote them), writes normalized prob, accumulates ctx = P @ V.
__global__ void __launch_bounds__(256) attn_kernel(
    const void* __restrict__ mask, float* __restrict__ prob) {

    __shared__ float qp_s[64 * 65];  // pass1: qT (stride 64) / pass2: P tile (stride 65)
    __shared__ float kv_s[64 * 64];  // pass1: kT / pass2: V tile

    const int tid = threadIdx.x, tx = tid & 15, ty = tid >> 4;
    const int bh = blockIdx.y, q0 = blockIdx.x * 64;
    const int bI = bh >> 4, hI = bh & 15;

    const float* qg = g_q + (size_t)bh * S_ * D_ + (size_t)q0 * D_;
    const float* kg = g_k + (size_t)bh * S_ * D_;
    const float* vg = g_v + (size_t)bh * S_ * D_;
    float* sc = prob + ((size_t)bh * S_ + q0) * S_;
    const int mm = g_mask_mode;

    // load qT (scaled)
#pragma unroll
    for (int i = 0; i < 4; i++) {
        int idx = tid + i * 256;
        int r = idx >> 4, dq = (idx & 15) << 2;
        float4 v = *(const float4*)(qg + r * 64 + dq);
        qp_s[(dq + 0) * 64 + r] = v.x * SCALE_;
        qp_s[(dq + 1) * 64 + r] = v.y * SCALE_;
        qp_s[(dq + 2) * 64 + r] = v.z * SCALE_;
        qp_s[(dq + 3) * 64 + r] = v.w * SCALE_;
    }
    __syncthreads();

    float m[4] = {-1e30f, -1e30f, -1e30f, -1e30f};
    float l[4] = {0.f, 0.f, 0.f, 0.f};

    // ---------------- pass 1: scores + online (m,l) ----------------------
    for (int kt = 0; kt < 32; kt++) {
        const int k0 = kt * 64;
#pragma unroll
        for (int i = 0; i < 4; i++) {          // load kT tile
            int idx = tid + i * 256;
            int r = idx >> 4, dq = (idx & 15) << 2;
            float4 v = *(const float4*)(kg + (size_t)(k0 + r) * 64 + dq);
            kv_s[(dq + 0) * 64 + r] = v.x;
            kv_s[(dq + 1) * 64 + r] = v.y;
            kv_s[(dq + 2) * 64 + r] = v.z;
            kv_s[(dq + 3) * 64 + r] = v.w;
        }
        __syncthreads();

        float acc[4][4] = {};
#pragma unroll 16
        for (int d = 0; d < 64; d++) {
            float4 a4 = *(const float4*)(qp_s + d * 64 + ty * 4);
            float4 b4 = *(const float4*)(kv_s + d * 64 + tx * 4);
            float av[4] = {a4.x, a4.y, a4.z, a4.w};
            float bv[4] = {b4.x, b4.y, b4.z, b4.w};
#pragma unroll
            for (int ir = 0; ir < 4; ir++)
#pragma unroll
                for (int jc = 0; jc < 4; jc++)
                    acc[ir][jc] = fmaf(av[ir], bv[jc], acc[ir][jc]);
        }

#pragma unroll
        for (int ir = 0; ir < 4; ir++) {
            int row = ty * 4 + ir;
            size_t moff = ((size_t)bI * S_ + q0 + row) * S_ + k0 + tx * 4;
            if (mm == 0) {
                uchar4 u = *(const uchar4*)((const unsigned char*)mask + moff);
                if (u.x) acc[ir][0] = NEG_;
                if (u.y) acc[ir][1] = NEG_;
                if (u.z) acc[ir][2] = NEG_;
                if (u.w) acc[ir][3] = NEG_;
            } else if (mm == 1) {
                int4 u = *(const int4*)((const int*)mask + moff);
                if (u.x) acc[ir][0] = NEG_;
                if (u.y) acc[ir][1] = NEG_;
                if (u.z) acc[ir][2] = NEG_;
                if (u.w) acc[ir][3] = NEG_;
            } else {
                float4 u = *(const float4*)((const float*)mask + moff);
                if (u.x != 0.f) acc[ir][0] = NEG_;
                if (u.y != 0.f) acc[ir][1] = NEG_;
                if (u.z != 0.f) acc[ir][2] = NEG_;
                if (u.w != 0.f) acc[ir][3] = NEG_;
            }
            float tm = fmaxf(fmaxf(acc[ir][0], acc[ir][1]),
                             fmaxf(acc[ir][2], acc[ir][3]));
#pragma unroll
            for (int o = 8; o; o >>= 1)
                tm = fmaxf(tm, __shfl_xor_sync(0xffffffffu, tm, o));
            float mn = fmaxf(m[ir], tm);
            float ps = __expf(acc[ir][0] - mn) + __expf(acc[ir][1] - mn)
                     + __expf(acc[ir][2] - mn) + __expf(acc[ir][3] - mn);
#pragma unroll
            for (int o = 8; o; o >>= 1)
                ps += __shfl_xor_sync(0xffffffffu, ps, o);
            l[ir] = l[ir] * __expf(m[ir] - mn) + ps;
            m[ir] = mn;
            *(float4*)(sc + (size_t)row * S_ + k0 + tx * 4) =
                make_float4(acc[ir][0], acc[ir][1], acc[ir][2], acc[ir][3]);
        }
        __syncthreads();
    }

    // ---------------- pass 2: normalize prob + ctx = P @ V ---------------
    float il[4];
#pragma unroll
    for (int ir = 0; ir < 4; ir++) il[ir] = 1.0f / l[ir];
    float ctx[4][4] = {};

    for (int kt = 0; kt < 32; kt++) {
        const int k0 = kt * 64;
#pragma unroll
        for (int i = 0; i < 4; i++) {          // V tile (contiguous copy)
            int idx = tid + i * 256;
            ((float4*)kv_s)[idx] = ((const float4*)(vg + (size_t)k0 * 64))[idx];
        }
#pragma unroll
        for (int ir = 0; ir < 4; ir++) {
            int row = ty * 4 + ir;
            float* sp = sc + (size_t)row * S_ + k0 + tx * 4;
            float4 s4 = *(const float4*)sp;
            float4 p4;
            p4.x = __expf(s4.x - m[ir]) * il[ir];
            p4.y = __expf(s4.y - m[ir]) * il[ir];
            p4.z = __expf(s4.z - m[ir]) * il[ir];
            p4.w = __expf(s4.w - m[ir]) * il[ir];
            *(float4*)sp = p4;                 // final prob output
            float* pr = qp_s + row * 65 + tx * 4;
            pr[0] = p4.x; pr[1] = p4.y; pr[2] = p4.z; pr[3] = p4.w;
        }
        __syncthreads();

#pragma unroll 16
        for (int kk = 0; kk < 64; kk++) {
            float4 v4 = *(const float4*)(kv_s + kk * 64 + tx * 4);
            float pv0 = qp_s[(ty * 4 + 0) * 65 + kk];
            float pv1 = qp_s[(ty * 4 + 1) * 65 + kk];
            float pv2 = qp_s[(ty * 4 + 2) * 65 + kk];
            float pv3 = qp_s[(ty * 4 + 3) * 65 + kk];
            ctx[0][0] = fmaf(pv0, v4.x, ctx[0][0]);
            ctx[0][1] = fmaf(pv0, v4.y, ctx[0][1]);
            ctx[0][2] = fmaf(pv0, v4.z, ctx[0][2]);
            ctx[0][3] = fmaf(pv0, v4.w, ctx[0][3]);
            ctx[1][0] = fmaf(pv1, v4.x, ctx[1][0]);
            ctx[1][1] = fmaf(pv1, v4.y, ctx[1][1]);
            ctx[1][2] = fmaf(pv1, v4.z, ctx[1][2]);
            ctx[1][3] = fmaf(pv1, v4.w, ctx[1][3]);
            ctx[2][0] = fmaf(pv2, v4.x, ctx[2][0]);
            ctx[2][1] = fmaf(pv2, v4.y, ctx[2][1]);
            ctx[2][2] = fmaf(pv2, v4.z, ctx[2][2]);
            ctx[2][3] = fmaf(pv2, v4.w, ctx[2][3]);
            ctx[3][0] = fmaf(pv3, v4.x, ctx[3][0]);
            ctx[3][1] = fmaf(pv3, v4.y, ctx[3][1]);
            ctx[3][2] = fmaf(pv3, v4.z, ctx[3][2]);
            ctx[3][3] = fmaf(pv3, v4.w, ctx[3][3]);
        }
        __syncthreads();
    }

#pragma unroll
    for (int ir = 0; ir < 4; ir++) {
        int row = q0 + ty * 4 + ir;
        *(float4*)(g_ctx + ((size_t)bI * S_ + row) * HD_ + hI * 64 + tx * 4) =
            make_float4(ctx[ir][0], ctx[ir][1], ctx[ir][2], ctx[ir][3]);
    }
}

// ---------------- launcher ------------------------------------------------
extern "C" void kernel_launch(void* const* d_in, const int* in_sizes, int n_in,
                              void* d_out, int out_size) {
    const float* Q  = (const float*)d_in[0];
    const float* K  = (const float*)d_in[1];
    const float* V  = (const float*)d_in[2];
    const void*  mask = d_in[3];
    const float* WQ = (const float*)d_in[4];
    const float* bQ = (const float*)d_in[5];
    const float* WK = (const float*)d_in[6];
    const float* bK = (const float*)d_in[7];
    const float* WV = (const float*)d_in[8];
    const float* bV = (const float*)d_in[9];
    const float* WO = (const float*)d_in[10];
    const float* bO = (const float*)d_in[11];

    float* y    = (float*)d_out;
    float* prob = y + (size_t)N_ * E_;

    dim3 blk(256);
    dim3 gproj(HD_ / 64, N_ / 64);

    gemm_kernel<<<gproj, blk>>>(Q, WQ, bQ, nullptr, 0);
    gemm_kernel<<<gproj, blk>>>(K, WK, bK, nullptr, 1);
    gemm_kernel<<<gproj, blk>>>(V, WV, bV, nullptr, 2);
    detect_mask_kernel<<<1, 256>>>((const unsigned int*)mask);
    attn_kernel<<<dim3(S_ / 64, B_ * H_), blk>>>(mask, prob);
    gemm_kernel<<<gproj, blk>>>(nullptr, WO, bO, y, 3);
}

// round 4
// speedup vs baseline: 1.0181x; 1.0181x over previous
#include <cuda_runtime.h>
#include <cstdint>

// Problem constants
#define B_   2
#define S_   2048
#define E_   1024
#define H_   16
#define D_   64
#define HD_  1024
#define N_   4096            // B*S
#define SCALE_ 0.125f        // 1/sqrt(64)
#define NEG_  -1e9f

// ---------------- scratch (device globals; no allocations allowed) -------
__device__ float g_q[(size_t)B_ * H_ * S_ * D_];    // [bh][s][d]
__device__ float g_k[(size_t)B_ * H_ * S_ * D_];
__device__ float g_v[(size_t)B_ * H_ * S_ * D_];
__device__ float g_ctx[(size_t)N_ * HD_];           // [b*S+s][h*D+d]
__device__ int   g_mask_mode;                       // 0=u8, 1=i32, 2=f32

// ---------------- mma.sync helpers (sm_80+, works on plain sm_100) -------
__device__ __forceinline__ uint32_t f2tf32(float x) {
    uint32_t r;
    asm("cvt.rna.tf32.f32 %0, %1;" : "=r"(r) : "f"(x));
    return r;
}
__device__ __forceinline__ void mma_tf32(float* c, const uint32_t* a,
                                         const uint32_t* b) {
    asm volatile(
        "mma.sync.aligned.m16n8k8.row.col.f32.tf32.tf32.f32 "
        "{%0,%1,%2,%3}, {%4,%5,%6,%7}, {%8,%9}, {%0,%1,%2,%3};"
        : "+f"(c[0]), "+f"(c[1]), "+f"(c[2]), "+f"(c[3])
        : "r"(a[0]), "r"(a[1]), "r"(a[2]), "r"(a[3]), "r"(b[0]), "r"(b[1]));
}

// ---------------- mask dtype detector ------------------------------------
__global__ void detect_mask_kernel(const unsigned int* __restrict__ m) {
    unsigned int v = m[threadIdx.x];
    int isf = (v == 0x3F800000u);
    int big = (v > 1u);
    isf = __syncthreads_or(isf);
    big = __syncthreads_or(big);
    if (threadIdx.x == 0) g_mask_mode = isf ? 2 : (big ? 0 : 1);
}

// ============ tensor-core tf32 GEMM: out = A[4096,1024]@W[1024,1024]+b ====
// CTA tile 128x128, 8 warps (2m x 4n), warp tile 64x32 = 4x4 m16n8k8 tiles.
// Smem holds fragment-ordered tf32 tiles (conflict-free LDS.128/LDS.64),
// double-buffered K chunks of 32.
//
// A frag layout  (per 16x8 tile): float off = mt*512 + kt*128 + lane*4 + reg
//   lane = g*4+tig holds a0:(g,tig) a1:(g+8,tig) a2:(g,tig+4) a3:(g+8,tig+4)
// B frag layout  (per 8x8 tile):  float off = nt*256 + kt*64 + lane*2 + reg
//   lane = g*4+tig holds b0:(k=tig, n=g) b1:(k=tig+4, n=g)
#define GEMM_SMEM_BYTES 65536

__global__ void __launch_bounds__(256) gemm_tc_kernel(
    const float* __restrict__ Ain, const float* __restrict__ W,
    const float* __restrict__ bias, float* __restrict__ outp, int sel) {

    extern __shared__ float smf[];   // [0..8192) A bufs, [8192..16384) B bufs

    const int tid = threadIdx.x;
    const int wid = tid >> 5, lane = tid & 31;
    const int m0 = blockIdx.y * 128, c0 = blockIdx.x * 128;
    const int warpM = wid & 1, warpN = wid >> 1;
    const int g = lane >> 2, tig = lane & 3;

    const float* A = (sel == 3) ? g_ctx : Ain;
    float* dst = (sel == 0) ? g_q : (sel == 1) ? g_k : (sel == 2) ? g_v : outp;

    // ---- loader index precompute (4 float4 each for A and B tile) --------
    // A tile: 128 rows x 32 k.  idx -> r = idx>>3, colquad q = idx&7
    int a_r[4], a_q[4], b_k[4], b_n[4];
#pragma unroll
    for (int i = 0; i < 4; i++) {
        int idx = tid + i * 256;
        a_r[i] = idx >> 3;  a_q[i] = idx & 7;
        b_k[i] = idx >> 5;  b_n[i] = (idx & 31) << 2;
    }

    float4 aregs[4], bregs[4];
    auto ldg_chunk = [&](int k0) {
#pragma unroll
        for (int i = 0; i < 4; i++) {
            aregs[i] = *(const float4*)(A + (size_t)(m0 + a_r[i]) * E_ + k0 + a_q[i] * 4);
            bregs[i] = *(const float4*)(W + (size_t)(k0 + b_k[i]) * HD_ + c0 + b_n[i]);
        }
    };
    auto sts_chunk = [&](int buf) {
        float* ab = smf + buf * 4096;
        float* bb = smf + 8192 + buf * 4096;
#pragma unroll
        for (int i = 0; i < 4; i++) {
            // A element (r, c= q*4+e)
            int r = a_r[i], q = a_q[i];
            int mt = r >> 4, rr = r & 15;
            int gg = rr & 7, hi = rr >> 3;
            int kt = q >> 1, chalf = q & 1;
            int base = mt * 512 + kt * 128 + gg * 16 + hi + 2 * chalf;
            float v[4] = {aregs[i].x, aregs[i].y, aregs[i].z, aregs[i].w};
#pragma unroll
            for (int e = 0; e < 4; e++)
                ((uint32_t*)ab)[base + e * 4] = f2tf32(v[e]);
            // B element (k, n = b_n+e)
            int kk = b_k[i], n = b_n[i];
            int bkt = kk >> 3, kkr = kk & 7;
            int btig = kkr & 3, khalf = kkr >> 2;
            int nt = n >> 3, gb = n & 7;
            int bbase = nt * 256 + bkt * 64 + (gb * 4 + btig) * 2 + khalf;
            float w[4] = {bregs[i].x, bregs[i].y, bregs[i].z, bregs[i].w};
#pragma unroll
            for (int e = 0; e < 4; e++)
                ((uint32_t*)bb)[bbase + e * 8] = f2tf32(w[e]);
        }
    };

    float c[4][4][4] = {};

    ldg_chunk(0);
    sts_chunk(0);
    __syncthreads();

    for (int ch = 0; ch < 32; ch++) {
        const int buf = ch & 1;
        if (ch < 31) ldg_chunk((ch + 1) * 32);

        const uint32_t* ab = (const uint32_t*)(smf + buf * 4096);
        const uint32_t* bb = (const uint32_t*)(smf + 8192 + buf * 4096);
#pragma unroll
        for (int kt = 0; kt < 4; kt++) {
            uint32_t af[4][4];
            uint32_t bf[4][2];
#pragma unroll
            for (int i = 0; i < 4; i++) {
                uint4 t = *(const uint4*)(ab + (warpM * 4 + i) * 512 + kt * 128 + lane * 4);
                af[i][0] = t.x; af[i][1] = t.y; af[i][2] = t.z; af[i][3] = t.w;
            }
#pragma unroll
            for (int j = 0; j < 4; j++) {
                uint2 t = *(const uint2*)(bb + (warpN * 4 + j) * 256 + kt * 64 + lane * 2);
                bf[j][0] = t.x; bf[j][1] = t.y;
            }
#pragma unroll
            for (int i = 0; i < 4; i++)
#pragma unroll
                for (int j = 0; j < 4; j++)
                    mma_tf32(c[i][j], af[i], bf[j]);
        }

        if (ch < 31) sts_chunk(buf ^ 1);
        __syncthreads();
    }

    // ---- epilogue: bias add + (optional) BHSD layout transform -----------
#pragma unroll
    for (int i = 0; i < 4; i++) {
        int rtop = m0 + warpM * 64 + i * 16 + g;
        int rbot = rtop + 8;
#pragma unroll
        for (int j = 0; j < 4; j++) {
            int coln = c0 + warpN * 32 + j * 8 + tig * 2;
            float2 bb2 = *(const float2*)(bias + coln);
            float2 t0 = make_float2(c[i][j][0] + bb2.x, c[i][j][1] + bb2.y);
            float2 t1 = make_float2(c[i][j][2] + bb2.x, c[i][j][3] + bb2.y);
            if (sel < 3) {
                int hI = coln >> 6, dI = coln & 63;
                int b0I = rtop >> 11, s0I = rtop & (S_ - 1);
                int b1I = rbot >> 11, s1I = rbot & (S_ - 1);
                *(float2*)(dst + (((size_t)b0I * H_ + hI) * S_ + s0I) * D_ + dI) = t0;
                *(float2*)(dst + (((size_t)b1I * H_ + hI) * S_ + s1I) * D_ + dI) = t1;
            } else {
                *(float2*)(dst + (size_t)rtop * HD_ + coln) = t0;
                *(float2*)(dst + (size_t)rbot * HD_ + coln) = t1;
            }
        }
    }
}

// ---------------- attention: scores->softmax->prob + context -------------
__global__ void __launch_bounds__(256) attn_kernel(
    const void* __restrict__ mask, float* __restrict__ prob) {

    __shared__ float qp_s[64 * 65];
    __shared__ float kv_s[64 * 64];

    const int tid = threadIdx.x, tx = tid & 15, ty = tid >> 4;
    const int bh = blockIdx.y, q0 = blockIdx.x * 64;
    const int bI = bh >> 4, hI = bh & 15;

    const float* qg = g_q + (size_t)bh * S_ * D_ + (size_t)q0 * D_;
    const float* kg = g_k + (size_t)bh * S_ * D_;
    const float* vg = g_v + (size_t)bh * S_ * D_;
    float* sc = prob + ((size_t)bh * S_ + q0) * S_;
    const int mm = g_mask_mode;

#pragma unroll
    for (int i = 0; i < 4; i++) {
        int idx = tid + i * 256;
        int r = idx >> 4, dq = (idx & 15) << 2;
        float4 v = *(const float4*)(qg + r * 64 + dq);
        qp_s[(dq + 0) * 64 + r] = v.x * SCALE_;
        qp_s[(dq + 1) * 64 + r] = v.y * SCALE_;
        qp_s[(dq + 2) * 64 + r] = v.z * SCALE_;
        qp_s[(dq + 3) * 64 + r] = v.w * SCALE_;
    }
    __syncthreads();

    float m[4] = {-1e30f, -1e30f, -1e30f, -1e30f};
    float l[4] = {0.f, 0.f, 0.f, 0.f};

    for (int kt = 0; kt < 32; kt++) {
        const int k0 = kt * 64;
#pragma unroll
        for (int i = 0; i < 4; i++) {
            int idx = tid + i * 256;
            int r = idx >> 4, dq = (idx & 15) << 2;
            float4 v = *(const float4*)(kg + (size_t)(k0 + r) * 64 + dq);
            kv_s[(dq + 0) * 64 + r] = v.x;
            kv_s[(dq + 1) * 64 + r] = v.y;
            kv_s[(dq + 2) * 64 + r] = v.z;
            kv_s[(dq + 3) * 64 + r] = v.w;
        }
        __syncthreads();

        float acc[4][4] = {};
#pragma unroll 16
        for (int d = 0; d < 64; d++) {
            float4 a4 = *(const float4*)(qp_s + d * 64 + ty * 4);
            float4 b4 = *(const float4*)(kv_s + d * 64 + tx * 4);
            float av[4] = {a4.x, a4.y, a4.z, a4.w};
            float bv[4] = {b4.x, b4.y, b4.z, b4.w};
#pragma unroll
            for (int ir = 0; ir < 4; ir++)
#pragma unroll
                for (int jc = 0; jc < 4; jc++)
                    acc[ir][jc] = fmaf(av[ir], bv[jc], acc[ir][jc]);
        }

#pragma unroll
        for (int ir = 0; ir < 4; ir++) {
            int row = ty * 4 + ir;
            size_t moff = ((size_t)bI * S_ + q0 + row) * S_ + k0 + tx * 4;
            if (mm == 0) {
                uchar4 u = *(const uchar4*)((const unsigned char*)mask + moff);
                if (u.x) acc[ir][0] = NEG_;
                if (u.y) acc[ir][1] = NEG_;
                if (u.z) acc[ir][2] = NEG_;
                if (u.w) acc[ir][3] = NEG_;
            } else if (mm == 1) {
                int4 u = *(const int4*)((const int*)mask + moff);
                if (u.x) acc[ir][0] = NEG_;
                if (u.y) acc[ir][1] = NEG_;
                if (u.z) acc[ir][2] = NEG_;
                if (u.w) acc[ir][3] = NEG_;
            } else {
                float4 u = *(const float4*)((const float*)mask + moff);
                if (u.x != 0.f) acc[ir][0] = NEG_;
                if (u.y != 0.f) acc[ir][1] = NEG_;
                if (u.z != 0.f) acc[ir][2] = NEG_;
                if (u.w != 0.f) acc[ir][3] = NEG_;
            }
            float tm = fmaxf(fmaxf(acc[ir][0], acc[ir][1]),
                             fmaxf(acc[ir][2], acc[ir][3]));
#pragma unroll
            for (int o = 8; o; o >>= 1)
                tm = fmaxf(tm, __shfl_xor_sync(0xffffffffu, tm, o));
            float mn = fmaxf(m[ir], tm);
            float ps = __expf(acc[ir][0] - mn) + __expf(acc[ir][1] - mn)
                     + __expf(acc[ir][2] - mn) + __expf(acc[ir][3] - mn);
#pragma unroll
            for (int o = 8; o; o >>= 1)
                ps += __shfl_xor_sync(0xffffffffu, ps, o);
            l[ir] = l[ir] * __expf(m[ir] - mn) + ps;
            m[ir] = mn;
            *(float4*)(sc + (size_t)row * S_ + k0 + tx * 4) =
                make_float4(acc[ir][0], acc[ir][1], acc[ir][2], acc[ir][3]);
        }
        __syncthreads();
    }

    float il[4];
#pragma unroll
    for (int ir = 0; ir < 4; ir++) il[ir] = 1.0f / l[ir];
    float ctx[4][4] = {};

    for (int kt = 0; kt < 32; kt++) {
        const int k0 = kt * 64;
#pragma unroll
        for (int i = 0; i < 4; i++) {
            int idx = tid + i * 256;
            ((float4*)kv_s)[idx] = ((const float4*)(vg + (size_t)k0 * 64))[idx];
        }
#pragma unroll
        for (int ir = 0; ir < 4; ir++) {
            int row = ty * 4 + ir;
            float* sp = sc + (size_t)row * S_ + k0 + tx * 4;
            float4 s4 = *(const float4*)sp;
            float4 p4;
            p4.x = __expf(s4.x - m[ir]) * il[ir];
            p4.y = __expf(s4.y - m[ir]) * il[ir];
            p4.z = __expf(s4.z - m[ir]) * il[ir];
            p4.w = __expf(s4.w - m[ir]) * il[ir];
            *(float4*)sp = p4;
            float* pr = qp_s + row * 65 + tx * 4;
            pr[0] = p4.x; pr[1] = p4.y; pr[2] = p4.z; pr[3] = p4.w;
        }
        __syncthreads();

#pragma unroll 16
        for (int kk = 0; kk < 64; kk++) {
            float4 v4 = *(const float4*)(kv_s + kk * 64 + tx * 4);
            float pv0 = qp_s[(ty * 4 + 0) * 65 + kk];
            float pv1 = qp_s[(ty * 4 + 1) * 65 + kk];
            float pv2 = qp_s[(ty * 4 + 2) * 65 + kk];
            float pv3 = qp_s[(ty * 4 + 3) * 65 + kk];
            ctx[0][0] = fmaf(pv0, v4.x, ctx[0][0]);
            ctx[0][1] = fmaf(pv0, v4.y, ctx[0][1]);
            ctx[0][2] = fmaf(pv0, v4.z, ctx[0][2]);
            ctx[0][3] = fmaf(pv0, v4.w, ctx[0][3]);
            ctx[1][0] = fmaf(pv1, v4.x, ctx[1][0]);
            ctx[1][1] = fmaf(pv1, v4.y, ctx[1][1]);
            ctx[1][2] = fmaf(pv1, v4.z, ctx[1][2]);
            ctx[1][3] = fmaf(pv1, v4.w, ctx[1][3]);
            ctx[2][0] = fmaf(pv2, v4.x, ctx[2][0]);
            ctx[2][1] = fmaf(pv2, v4.y, ctx[2][1]);
            ctx[2][2] = fmaf(pv2, v4.z, ctx[2][2]);
            ctx[2][3] = fmaf(pv2, v4.w, ctx[2][3]);
            ctx[3][0] = fmaf(pv3, v4.x, ctx[3][0]);
            ctx[3][1] = fmaf(pv3, v4.y, ctx[3][1]);
            ctx[3][2] = fmaf(pv3, v4.z, ctx[3][2]);
            ctx[3][3] = fmaf(pv3, v4.w, ctx[3][3]);
        }
        __syncthreads();
    }

#pragma unroll
    for (int ir = 0; ir < 4; ir++) {
        int row = q0 + ty * 4 + ir;
        *(float4*)(g_ctx + ((size_t)bI * S_ + row) * HD_ + hI * 64 + tx * 4) =
            make_float4(ctx[ir][0], ctx[ir][1], ctx[ir][2], ctx[ir][3]);
    }
}

// ---------------- launcher ------------------------------------------------
extern "C" void kernel_launch(void* const* d_in, const int* in_sizes, int n_in,
                              void* d_out, int out_size) {
    const float* Q  = (const float*)d_in[0];
    const float* K  = (const float*)d_in[1];
    const float* V  = (const float*)d_in[2];
    const void*  mask = d_in[3];
    const float* WQ = (const float*)d_in[4];
    const float* bQ = (const float*)d_in[5];
    const float* WK = (const float*)d_in[6];
    const float* bK = (const float*)d_in[7];
    const float* WV = (const float*)d_in[8];
    const float* bV = (const float*)d_in[9];
    const float* WO = (const float*)d_in[10];
    const float* bO = (const float*)d_in[11];

    float* y    = (float*)d_out;
    float* prob = y + (size_t)N_ * E_;

    cudaFuncSetAttribute(gemm_tc_kernel,
                         cudaFuncAttributeMaxDynamicSharedMemorySize,
                         GEMM_SMEM_BYTES);

    dim3 blk(256);
    dim3 gproj(HD_ / 128, N_ / 128);   // (8, 32) tiles of 128x128

    gemm_tc_kernel<<<gproj, blk, GEMM_SMEM_BYTES>>>(Q, WQ, bQ, nullptr, 0);
    gemm_tc_kernel<<<gproj, blk, GEMM_SMEM_BYTES>>>(K, WK, bK, nullptr, 1);
    gemm_tc_kernel<<<gproj, blk, GEMM_SMEM_BYTES>>>(V, WV, bV, nullptr, 2);
    detect_mask_kernel<<<1, 256>>>((const unsigned int*)mask);
    attn_kernel<<<dim3(S_ / 64, B_ * H_), blk>>>(mask, prob);
    gemm_tc_kernel<<<gproj, blk, GEMM_SMEM_BYTES>>>(nullptr, WO, bO, y, 3);
}

// round 5
// speedup vs baseline: 2.2012x; 2.1621x over previous
#include <cuda_runtime.h>
#include <cuda_fp16.h>
#include <cstdint>

// Problem constants
#define B_   2
#define S_   2048
#define E_   1024
#define H_   16
#define D_   64
#define HD_  1024
#define N_   4096            // B*S
#define SCALE_ 0.125f        // 1/sqrt(64)
#define NEG_  -1e9f

// ---------------- scratch (device globals; no allocations allowed) -------
__device__ float g_q[(size_t)B_ * H_ * S_ * D_];    // [bh][s][d]
__device__ float g_k[(size_t)B_ * H_ * S_ * D_];
__device__ float g_v[(size_t)B_ * H_ * S_ * D_];
__device__ float g_ctx[(size_t)N_ * HD_];           // [b*S+s][h*D+d]
__device__ int   g_mask_mode;                       // 0=u8, 1=i32, 2=f32

// ---------------- mma.sync fp16 helpers (sm_80+ baseline ISA) ------------
__device__ __forceinline__ void mma_f16(float* c, const uint32_t* a,
                                        const uint32_t* b) {
    asm volatile(
        "mma.sync.aligned.m16n8k16.row.col.f32.f16.f16.f32 "
        "{%0,%1,%2,%3}, {%4,%5,%6,%7}, {%8,%9}, {%0,%1,%2,%3};"
        : "+f"(c[0]), "+f"(c[1]), "+f"(c[2]), "+f"(c[3])
        : "r"(a[0]), "r"(a[1]), "r"(a[2]), "r"(a[3]), "r"(b[0]), "r"(b[1]));
}
__device__ __forceinline__ uint32_t packh2(float x, float y) {
    __half2 h = __floats2half2_rn(x, y);
    return *(uint32_t*)&h;
}

// ---------------- mask dtype detector ------------------------------------
__global__ void detect_mask_kernel(const unsigned int* __restrict__ m) {
    unsigned int v = m[threadIdx.x];
    int isf = (v == 0x3F800000u);
    int big = (v > 1u);
    isf = __syncthreads_or(isf);
    big = __syncthreads_or(big);
    if (threadIdx.x == 0) g_mask_mode = isf ? 2 : (big ? 0 : 1);
}

// ============ fp16 tensor GEMM: out = A[4096,1024]@W[1024,1024]+bias ======
// CTA tile 128x128, 8 warps (2m x 4n), warp tile 64x32 = 4x4 m16n8k16 tiles,
// K chunks of 32 (2 k-steps), double-buffered fragment-ordered smem.
// A-frag word layout (16x16 tile = 128 u32): off = lane*4 + reg
//   reg = hi + 2*khalf; element (r,c): g=r&7, hi=(r>>3)&1, t=((c&15)>>1)&3,
//   khalf=(c&15)>>3, lane=g*4+t, halves pack (c even, c+1)
// B-frag word layout (8x16 tile = 64 u32): off = lane*2 + reg
//   reg = khalf; element (k,n): g=n&7, t=((k&15)>>1)&3, khalf=(k&15)>>3
__global__ void __launch_bounds__(256) gemm_tc_kernel(
    const float* __restrict__ Ain, const float* __restrict__ W,
    const float* __restrict__ bias, float* __restrict__ outp, int sel) {

    __shared__ uint32_t sA[2][2048];   // 8 mt x 2 kt tiles of 128 words
    __shared__ uint32_t sB[2][2048];   // 16 nt x 2 kt tiles of 64 words

    const int tid = threadIdx.x;
    const int wid = tid >> 5, lane = tid & 31;
    const int m0 = blockIdx.y * 128, c0 = blockIdx.x * 128;
    const int warpM = wid & 1, warpN = wid >> 1;
    const int g = lane >> 2, tq = lane & 3;

    const float* A = (sel == 3) ? g_ctx : Ain;
    float* dst = (sel == 0) ? g_q : (sel == 1) ? g_k : (sel == 2) ? g_v : outp;

    // A loader indices: 4 float4 per thread (row r, col quad q)
    int a_r[4], a_q[4];
#pragma unroll
    for (int i = 0; i < 4; i++) {
        int idx = tid + i * 256;
        a_r[i] = idx >> 3;  a_q[i] = idx & 7;
    }
    // B loader: k-pair (k0,k0+1) x 8 n
    const int b_nt = tid & 15;           // n tile (8 cols)
    const int b_kp = tid >> 4;           // k pair index 0..15
    const int b_k0 = b_kp * 2;

    float4 aregs[4], br0a, br0b, br1a, br1b;
    auto ldg_chunk = [&](int k0) {
#pragma unroll
        for (int i = 0; i < 4; i++)
            aregs[i] = *(const float4*)(A + (size_t)(m0 + a_r[i]) * E_ + k0 + a_q[i] * 4);
        const float* w0 = W + (size_t)(k0 + b_k0) * HD_ + c0 + b_nt * 8;
        br0a = *(const float4*)(w0);
        br0b = *(const float4*)(w0 + 4);
        br1a = *(const float4*)(w0 + HD_);
        br1b = *(const float4*)(w0 + HD_ + 4);
    };
    auto sts_chunk = [&](int buf) {
        uint32_t* ab = sA[buf];
        uint32_t* bb = sB[buf];
#pragma unroll
        for (int i = 0; i < 4; i++) {
            int r = a_r[i], q = a_q[i];
            int mt = r >> 4, gg = r & 7, hi = (r >> 3) & 1;
            int kt = q >> 2, t0 = (q & 1) * 2, khalf = (q & 3) >> 1;
            int reg = hi + 2 * khalf;
            int base = (mt * 2 + kt) * 128;
            ab[base + (gg * 4 + t0) * 4 + reg]     = packh2(aregs[i].x, aregs[i].y);
            ab[base + (gg * 4 + t0 + 1) * 4 + reg] = packh2(aregs[i].z, aregs[i].w);
        }
        {
            int kt = b_kp >> 3;
            int t = b_kp & 3, reg = (b_kp >> 2) & 1;
            int base = (b_nt * 2 + kt) * 64;
            float r0[8] = {br0a.x, br0a.y, br0a.z, br0a.w, br0b.x, br0b.y, br0b.z, br0b.w};
            float r1[8] = {br1a.x, br1a.y, br1a.z, br1a.w, br1b.x, br1b.y, br1b.z, br1b.w};
#pragma unroll
            for (int e = 0; e < 8; e++)
                bb[base + (e * 4 + t) * 2 + reg] = packh2(r0[e], r1[e]);
        }
    };

    float c[4][4][4] = {};

    ldg_chunk(0);
    sts_chunk(0);
    __syncthreads();

    for (int ch = 0; ch < 32; ch++) {
        const int buf = ch & 1;
        if (ch < 31) ldg_chunk((ch + 1) * 32);

        const uint32_t* ab = sA[buf];
        const uint32_t* bb = sB[buf];
#pragma unroll
        for (int kt = 0; kt < 2; kt++) {
            uint32_t af[4][4];
            uint32_t bf[4][2];
#pragma unroll
            for (int i = 0; i < 4; i++) {
                uint4 t4 = *(const uint4*)(ab + ((warpM * 4 + i) * 2 + kt) * 128 + lane * 4);
                af[i][0] = t4.x; af[i][1] = t4.y; af[i][2] = t4.z; af[i][3] = t4.w;
            }
#pragma unroll
            for (int j = 0; j < 4; j++) {
                uint2 t2 = *(const uint2*)(bb + ((warpN * 4 + j) * 2 + kt) * 64 + lane * 2);
                bf[j][0] = t2.x; bf[j][1] = t2.y;
            }
#pragma unroll
            for (int i = 0; i < 4; i++)
#pragma unroll
                for (int j = 0; j < 4; j++)
                    mma_f16(c[i][j], af[i], bf[j]);
        }

        if (ch < 31) sts_chunk(buf ^ 1);
        __syncthreads();
    }

    // ---- epilogue: bias add + (optional) BHSD layout transform -----------
#pragma unroll
    for (int i = 0; i < 4; i++) {
        int rtop = m0 + warpM * 64 + i * 16 + g;
        int rbot = rtop + 8;
#pragma unroll
        for (int j = 0; j < 4; j++) {
            int coln = c0 + warpN * 32 + j * 8 + tq * 2;
            float2 bb2 = *(const float2*)(bias + coln);
            float2 t0 = make_float2(c[i][j][0] + bb2.x, c[i][j][1] + bb2.y);
            float2 t1 = make_float2(c[i][j][2] + bb2.x, c[i][j][3] + bb2.y);
            if (sel < 3) {
                int hI = coln >> 6, dI = coln & 63;
                int b0I = rtop >> 11, s0I = rtop & (S_ - 1);
                int b1I = rbot >> 11, s1I = rbot & (S_ - 1);
                *(float2*)(dst + (((size_t)b0I * H_ + hI) * S_ + s0I) * D_ + dI) = t0;
                *(float2*)(dst + (((size_t)b1I * H_ + hI) * S_ + s1I) * D_ + dI) = t1;
            } else {
                *(float2*)(dst + (size_t)rtop * HD_ + coln) = t0;
                *(float2*)(dst + (size_t)rbot * HD_ + coln) = t1;
            }
        }
    }
}

// ---------------- attention: fp16 mma QK^T / PV + exact softmax ----------
// grid (S/64, B*H), 256 threads = 8 warps (2m x 4n).
// Pass 1: per 64-k tile, K -> B-frags, mma scores -> smem scratch, then the
// scalar mask/online-(m,l)/raw-score-store logic (unchanged from the proven
// SIMT kernel) runs on the scratch. Pass 2: P -> A-frags, V -> B-frags,
// mma accumulates ctx in persistent C-fragments.
__global__ void __launch_bounds__(256) attn_kernel(
    const void* __restrict__ mask, float* __restrict__ prob) {

    __shared__ uint32_t sQP[2048];   // Q (pass1) / P (pass2): 4 mt x 4 kt A-tiles
    __shared__ uint32_t sKV[2048];   // K / V: 8 nt x 4 kt B-tiles
    __shared__ float    sS[64 * 68]; // 64x64 score scratch, stride 68

    const int tid = threadIdx.x, tx = tid & 15, ty = tid >> 4;
    const int wid = tid >> 5, lane = tid & 31;
    const int warpM = wid & 1, warpN = wid >> 1;
    const int g = lane >> 2, tq = lane & 3;
    const int bh = blockIdx.y, q0 = blockIdx.x * 64;
    const int bI = bh >> 4, hI = bh & 15;

    const float* qg = g_q + (size_t)bh * S_ * D_ + (size_t)q0 * D_;
    const float* kg = g_k + (size_t)bh * S_ * D_;
    const float* vg = g_v + (size_t)bh * S_ * D_;
    float* sc = prob + ((size_t)bh * S_ + q0) * S_;
    const int mm = g_mask_mode;

    // ---- load Q tile (scaled) into A-frag layout -------------------------
#pragma unroll
    for (int i = 0; i < 4; i++) {
        int idx = tid + i * 256;
        int r = idx >> 4, q = idx & 15;          // row, col-quad (c = q*4)
        float4 v = *(const float4*)(qg + r * 64 + q * 4);
        int mt = r >> 4, gg = r & 7, hi = (r >> 3) & 1;
        int kt = q >> 2, t0 = (q & 1) * 2, khalf = (q & 3) >> 1;
        int reg = hi + 2 * khalf;
        int base = (mt * 4 + kt) * 128;
        sQP[base + (gg * 4 + t0) * 4 + reg]     = packh2(v.x * SCALE_, v.y * SCALE_);
        sQP[base + (gg * 4 + t0 + 1) * 4 + reg] = packh2(v.z * SCALE_, v.w * SCALE_);
    }
    __syncthreads();

    float m[4] = {-1e30f, -1e30f, -1e30f, -1e30f};
    float l[4] = {0.f, 0.f, 0.f, 0.f};

    // =================== pass 1: scores + online (m,l) ====================
    for (int kt0 = 0; kt0 < 32; kt0++) {
        const int k0 = kt0 * 64;
        // K tile -> B-frags: word pairs along d (contiguous), n = k-row
#pragma unroll
        for (int i = 0; i < 4; i++) {
            int idx = tid + i * 256;
            int n = idx >> 4, q = idx & 15;
            float4 v = *(const float4*)(kg + (size_t)(k0 + n) * 64 + q * 4);
            int nt = n >> 3, gg = n & 7;
            int kt = q >> 2, t0 = (q & 1) * 2, reg = (q & 3) >> 1;
            int base = (nt * 4 + kt) * 64;
            sKV[base + (gg * 4 + t0) * 2 + reg]     = packh2(v.x, v.y);
            sKV[base + (gg * 4 + t0 + 1) * 2 + reg] = packh2(v.z, v.w);
        }
        __syncthreads();

        // mma: 64x64 scores, warp tile 32x16
        float cs[2][2][4] = {};
#pragma unroll
        for (int kt = 0; kt < 4; kt++) {
            uint32_t af[2][4];
            uint32_t bf[2][2];
#pragma unroll
            for (int i = 0; i < 2; i++) {
                uint4 t4 = *(const uint4*)(sQP + ((warpM * 2 + i) * 4 + kt) * 128 + lane * 4);
                af[i][0] = t4.x; af[i][1] = t4.y; af[i][2] = t4.z; af[i][3] = t4.w;
            }
#pragma unroll
            for (int j = 0; j < 2; j++) {
                uint2 t2 = *(const uint2*)(sKV + ((warpN * 2 + j) * 4 + kt) * 64 + lane * 2);
                bf[j][0] = t2.x; bf[j][1] = t2.y;
            }
#pragma unroll
            for (int i = 0; i < 2; i++)
#pragma unroll
                for (int j = 0; j < 2; j++)
                    mma_f16(cs[i][j], af[i], bf[j]);
        }
        // dump C-frags to score scratch
#pragma unroll
        for (int i = 0; i < 2; i++) {
            int r0 = warpM * 32 + i * 16 + g;
#pragma unroll
            for (int j = 0; j < 2; j++) {
                int cl = warpN * 16 + j * 8 + tq * 2;
                *(float2*)(sS + r0 * 68 + cl)       = make_float2(cs[i][j][0], cs[i][j][1]);
                *(float2*)(sS + (r0 + 8) * 68 + cl) = make_float2(cs[i][j][2], cs[i][j][3]);
            }
        }
        __syncthreads();

        // scalar block (unchanged semantics): mask, online max/sum, raw store
#pragma unroll
        for (int ir = 0; ir < 4; ir++) {
            int row = ty * 4 + ir;
            float4 s4 = *(const float4*)(sS + row * 68 + tx * 4);
            float acc[4] = {s4.x, s4.y, s4.z, s4.w};
            size_t moff = ((size_t)bI * S_ + q0 + row) * S_ + k0 + tx * 4;
            if (mm == 0) {
                uchar4 u = *(const uchar4*)((const unsigned char*)mask + moff);
                if (u.x) acc[0] = NEG_;
                if (u.y) acc[1] = NEG_;
                if (u.z) acc[2] = NEG_;
                if (u.w) acc[3] = NEG_;
            } else if (mm == 1) {
                int4 u = *(const int4*)((const int*)mask + moff);
                if (u.x) acc[0] = NEG_;
                if (u.y) acc[1] = NEG_;
                if (u.z) acc[2] = NEG_;
                if (u.w) acc[3] = NEG_;
            } else {
                float4 u = *(const float4*)((const float*)mask + moff);
                if (u.x != 0.f) acc[0] = NEG_;
                if (u.y != 0.f) acc[1] = NEG_;
                if (u.z != 0.f) acc[2] = NEG_;
                if (u.w != 0.f) acc[3] = NEG_;
            }
            float tm = fmaxf(fmaxf(acc[0], acc[1]), fmaxf(acc[2], acc[3]));
#pragma unroll
            for (int o = 8; o; o >>= 1)
                tm = fmaxf(tm, __shfl_xor_sync(0xffffffffu, tm, o));
            float mn = fmaxf(m[ir], tm);
            float ps = __expf(acc[0] - mn) + __expf(acc[1] - mn)
                     + __expf(acc[2] - mn) + __expf(acc[3] - mn);
#pragma unroll
            for (int o = 8; o; o >>= 1)
                ps += __shfl_xor_sync(0xffffffffu, ps, o);
            l[ir] = l[ir] * __expf(m[ir] - mn) + ps;
            m[ir] = mn;
            *(float4*)(sc + (size_t)row * S_ + k0 + tx * 4) =
                make_float4(acc[0], acc[1], acc[2], acc[3]);
        }
        __syncthreads();
    }

    // =================== pass 2: prob + ctx = P @ V =======================
    float il[4];
#pragma unroll
    for (int ir = 0; ir < 4; ir++) il[ir] = 1.0f / l[ir];
    float ctx[2][2][4] = {};

    for (int kt0 = 0; kt0 < 32; kt0++) {
        const int k0 = kt0 * 64;
        // V tile -> B-frags: word pairs along kk (rows), n = d
        {
            int kp = tid >> 3;                 // kk pair 0..31
            int kk0 = kp * 2;
            int d0 = (tid & 7) * 8;
            const float* vrow0 = vg + (size_t)(k0 + kk0) * 64 + d0;
            float4 r0a = *(const float4*)(vrow0);
            float4 r0b = *(const float4*)(vrow0 + 4);
            float4 r1a = *(const float4*)(vrow0 + 64);
            float4 r1b = *(const float4*)(vrow0 + 68);
            int nt = d0 >> 3;
            int kt = kk0 >> 4, t = kp & 3, reg = (kp >> 2) & 1;
            int base = (nt * 4 + kt) * 64;
            float r0[8] = {r0a.x, r0a.y, r0a.z, r0a.w, r0b.x, r0b.y, r0b.z, r0b.w};
            float r1[8] = {r1a.x, r1a.y, r1a.z, r1a.w, r1b.x, r1b.y, r1b.z, r1b.w};
#pragma unroll
            for (int e = 0; e < 8; e++)
                sKV[base + (e * 4 + t) * 2 + reg] = packh2(r0[e], r1[e]);
        }
        // P: read raw scores, exp-normalize, write prob + P A-frags
#pragma unroll
        for (int ir = 0; ir < 4; ir++) {
            int row = ty * 4 + ir;
            float* sp = sc + (size_t)row * S_ + k0 + tx * 4;
            float4 s4 = *(const float4*)sp;
            float4 p4;
            p4.x = __expf(s4.x - m[ir]) * il[ir];
            p4.y = __expf(s4.y - m[ir]) * il[ir];
            p4.z = __expf(s4.z - m[ir]) * il[ir];
            p4.w = __expf(s4.w - m[ir]) * il[ir];
            *(float4*)sp = p4;                  // final prob output
            int mt = row >> 4, gg = row & 7, hi = (row >> 3) & 1;
            int kt = tx >> 2, t0 = (tx & 1) * 2, khalf = (tx & 3) >> 1;
            int reg = hi + 2 * khalf;
            int base = (mt * 4 + kt) * 128;
            sQP[base + (gg * 4 + t0) * 4 + reg]     = packh2(p4.x, p4.y);
            sQP[base + (gg * 4 + t0 + 1) * 4 + reg] = packh2(p4.z, p4.w);
        }
        __syncthreads();

        // mma: ctx += P(64x64) @ V(64x64), warp tile 32x16
#pragma unroll
        for (int kt = 0; kt < 4; kt++) {
            uint32_t pf[2][4];
            uint32_t vf[2][2];
#pragma unroll
            for (int i = 0; i < 2; i++) {
                uint4 t4 = *(const uint4*)(sQP + ((warpM * 2 + i) * 4 + kt) * 128 + lane * 4);
                pf[i][0] = t4.x; pf[i][1] = t4.y; pf[i][2] = t4.z; pf[i][3] = t4.w;
            }
#pragma unroll
            for (int j = 0; j < 2; j++) {
                uint2 t2 = *(const uint2*)(sKV + ((warpN * 2 + j) * 4 + kt) * 64 + lane * 2);
                vf[j][0] = t2.x; vf[j][1] = t2.y;
            }
#pragma unroll
            for (int i = 0; i < 2; i++)
#pragma unroll
                for (int j = 0; j < 2; j++)
                    mma_f16(ctx[i][j], pf[i], vf[j]);
        }
        __syncthreads();
    }

    // ---- store ctx C-frags ------------------------------------------------
#pragma unroll
    for (int i = 0; i < 2; i++) {
        int r0 = q0 + warpM * 32 + i * 16 + g;
#pragma unroll
        for (int j = 0; j < 2; j++) {
            int cl = hI * 64 + warpN * 16 + j * 8 + tq * 2;
            *(float2*)(g_ctx + ((size_t)bI * S_ + r0) * HD_ + cl) =
                make_float2(ctx[i][j][0], ctx[i][j][1]);
            *(float2*)(g_ctx + ((size_t)bI * S_ + r0 + 8) * HD_ + cl) =
                make_float2(ctx[i][j][2], ctx[i][j][3]);
        }
    }
}

// ---------------- launcher ------------------------------------------------
extern "C" void kernel_launch(void* const* d_in, const int* in_sizes, int n_in,
                              void* d_out, int out_size) {
    const float* Q  = (const float*)d_in[0];
    const float* K  = (const float*)d_in[1];
    const float* V  = (const float*)d_in[2];
    const void*  mask = d_in[3];
    const float* WQ = (const float*)d_in[4];
    const float* bQ = (const float*)d_in[5];
    const float* WK = (const float*)d_in[6];
    const float* bK = (const float*)d_in[7];
    const float* WV = (const float*)d_in[8];
    const float* bV = (const float*)d_in[9];
    const float* WO = (const float*)d_in[10];
    const float* bO = (const float*)d_in[11];

    float* y    = (float*)d_out;
    float* prob = y + (size_t)N_ * E_;

    dim3 blk(256);
    dim3 gproj(HD_ / 128, N_ / 128);   // (8, 32) tiles of 128x128

    gemm_tc_kernel<<<gproj, blk>>>(Q, WQ, bQ, nullptr, 0);
    gemm_tc_kernel<<<gproj, blk>>>(K, WK, bK, nullptr, 1);
    gemm_tc_kernel<<<gproj, blk>>>(V, WV, bV, nullptr, 2);
    detect_mask_kernel<<<1, 256>>>((const unsigned int*)mask);
    attn_kernel<<<dim3(S_ / 64, B_ * H_), blk>>>(mask, prob);
    gemm_tc_kernel<<<gproj, blk>>>(nullptr, WO, bO, y, 3);
}